// round 6
// baseline (speedup 1.0000x reference)
#include <cuda_runtime.h>
#include <cuda_fp16.h>

#define N_USER    50000
#define N_ITEM    10000
#define NUM_NODES 60000
#define EMB_D     64
#define N_EDGES   2000000
#define N_WARPS   (N_EDGES / 32)   // 32 edges per warp

// Table scale: keeps fp16 products in normal range.
#define TBL_SCALE      512.0f
#define INV_TBL_SCALE2 (1.0f / (512.0f * 512.0f))   // 2^-18

// Fused, pre-scaled node table in fp16: row = 64 half = 128 B (one L1 line).
__device__ __half g_nodes[NUM_NODES * EMB_D];

// Phase 1: build fused node table (fp32 math, fp16 store, x512 pre-scale).
__global__ void build_nodes_kernel(const float* __restrict__ user_emb,
                                   const float* __restrict__ item_emb,
                                   const float* __restrict__ tag_emb,
                                   const float* __restrict__ testid_emb,
                                   const float* __restrict__ bigcat_emb,
                                   const float* __restrict__ daydiff_emb,
                                   const int*  __restrict__ item_tags,
                                   const int*  __restrict__ item_testids,
                                   const int*  __restrict__ item_bigcat,
                                   const int*  __restrict__ user_daydiff) {
    unsigned int t = blockIdx.x * blockDim.x + threadIdx.x;
    unsigned int node = t >> 4;
    unsigned int sub  = t & 15u;
    if (node >= NUM_NODES) return;
    unsigned int off = sub * 4u;

    const float alpha = 1.0f / 3.0f;
    float4 r;
    if (node < N_USER) {
        const float s = 0.5f * alpha * TBL_SCALE;
        int dd = user_daydiff[node];
        float4 u = *(const float4*)(user_emb    + (size_t)node * EMB_D + off);
        float4 d = *(const float4*)(daydiff_emb + (size_t)dd   * EMB_D + off);
        r.x = (u.x + d.x) * s;
        r.y = (u.y + d.y) * s;
        r.z = (u.z + d.z) * s;
        r.w = (u.w + d.w) * s;
    } else {
        const float s = 0.25f * alpha * TBL_SCALE;
        unsigned int it = node - N_USER;
        int tg = item_tags[it];
        int ts = item_testids[it];
        int bc = item_bigcat[it];
        float4 a = *(const float4*)(item_emb   + (size_t)it * EMB_D + off);
        float4 b = *(const float4*)(tag_emb    + (size_t)tg * EMB_D + off);
        float4 c = *(const float4*)(testid_emb + (size_t)ts * EMB_D + off);
        float4 e = *(const float4*)(bigcat_emb + (size_t)bc * EMB_D + off);
        r.x = (a.x + b.x + c.x + e.x) * s;
        r.y = (a.y + b.y + c.y + e.y) * s;
        r.z = (a.z + b.z + c.z + e.z) * s;
        r.w = (a.w + b.w + c.w + e.w) * s;
    }
    __half2 h0 = __floats2half2_rn(r.x, r.y);
    __half2 h1 = __floats2half2_rn(r.z, r.w);
    uint2 packed;
    packed.x = *(const unsigned int*)&h0;
    packed.y = *(const unsigned int*)&h1;
    *(uint2*)((char*)g_nodes + (size_t)node * 128u + sub * 8u) = packed;
}

__device__ __forceinline__ __half2 shfl_h2(__half2 v, int ofs) {
    unsigned int u = *(unsigned int*)&v;
    u = __shfl_xor_sync(0xffffffffu, u, ofs);
    return *(__half2*)&u;
}

// One value-halving reduction stage: 2W live values -> W, exchanging across
// lane-bit W. After the final stage lane l owns edge l of the warp's batch.
template <int W>
__device__ __forceinline__ void red_stage(__half2* p, unsigned int lane) {
    bool hi = (lane & (unsigned)W) != 0u;
#pragma unroll
    for (int i = 0; i < W; i++) {
        __half2 send = hi ? p[i] : p[i + W];
        __half2 keep = hi ? p[i + W] : p[i];
        p[i] = __hadd2(keep, shfl_h2(send, W));
    }
}

// Phase 2: 32 edges per warp. Every row gather is an LDG.32 with all 32 lanes
// inside ONE 128B line -> exactly one L1tex wavefront per load instruction
// (cross-LDG 1.0 cyc/wf instead of within-LDG 2.07 replay rate).
__global__ __launch_bounds__(256) void edge_dot_kernel(
        const int* __restrict__ src,
        const int* __restrict__ dst,
        float* __restrict__ out) {
    unsigned int gtid = blockIdx.x * blockDim.x + threadIdx.x;
    unsigned int warp = gtid >> 5;
    unsigned int lane = gtid & 31u;
    if (warp >= N_WARPS) return;
    unsigned int base = warp * 32u;

    // Lane l holds the endpoints of edge base+l (coalesced index loads).
    int my_s = src[base + lane];
    int my_d = dst[base + lane];

    const unsigned int* nodes = (const unsigned int*)g_nodes;  // row = 32 uints

    __half2 p[32];
#pragma unroll
    for (int e = 0; e < 32; e++) {
        unsigned int is = (unsigned int)__shfl_sync(0xffffffffu, my_s, e);
        unsigned int id = (unsigned int)__shfl_sync(0xffffffffu, my_d, e);
        unsigned int a = __ldg(nodes + is * 32u + lane);
        unsigned int b = __ldg(nodes + id * 32u + lane);
        p[e] = __hmul2(*(__half2*)&a, *(__half2*)&b);
    }

    red_stage<16>(p, lane);
    red_stage<8>(p, lane);
    red_stage<4>(p, lane);
    red_stage<2>(p, lane);
    red_stage<1>(p, lane);

    float2 f = __half22float2(p[0]);
    out[base + lane] = (f.x + f.y) * INV_TBL_SCALE2;   // coalesced 128B store
}

extern "C" void kernel_launch(void* const* d_in, const int* in_sizes, int n_in,
                              void* d_out, int out_size) {
    const float* user_emb     = (const float*)d_in[0];
    const float* item_emb     = (const float*)d_in[1];
    const float* tag_emb      = (const float*)d_in[2];
    const float* testid_emb   = (const float*)d_in[3];
    const float* bigcat_emb   = (const float*)d_in[4];
    const float* daydiff_emb  = (const float*)d_in[5];
    const int*   edge_index   = (const int*)d_in[6];   // [2, N_EDGES] int32
    const int*   item_tags    = (const int*)d_in[7];
    const int*   item_testids = (const int*)d_in[8];
    const int*   item_bigcat  = (const int*)d_in[9];
    const int*   user_daydiff = (const int*)d_in[10];

    // Phase 1: 60000 nodes * 16 threads
    {
        unsigned int total = NUM_NODES * 16u;
        unsigned int threads = 256;
        unsigned int blocks = (total + threads - 1) / threads;
        build_nodes_kernel<<<blocks, threads>>>(user_emb, item_emb, tag_emb,
                                                testid_emb, bigcat_emb, daydiff_emb,
                                                item_tags, item_testids, item_bigcat,
                                                user_daydiff);
    }

    // Phase 2: 62500 warps * 32 threads
    {
        unsigned int total = N_WARPS * 32u;
        unsigned int threads = 256;
        unsigned int blocks = (total + threads - 1) / threads;
        edge_dot_kernel<<<blocks, threads>>>(edge_index, edge_index + N_EDGES,
                                             (float*)d_out);
    }
}

// round 7
// speedup vs baseline: 2.5472x; 2.5472x over previous
#include <cuda_runtime.h>
#include <cuda_fp16.h>

#define N_USER    50000
#define N_ITEM    10000
#define NUM_NODES 60000
#define EMB_D     64
#define N_EDGES   2000000
#define N_GROUPS16 (N_EDGES / 16)   // 16 edges per 8-lane group

// Table scale: keeps fp16 products in normal range.
#define TBL_SCALE      512.0f
#define INV_TBL_SCALE2 (1.0f / (512.0f * 512.0f))   // 2^-18

// Fused, pre-scaled node table in fp16: row = 64 half = 128 B (one L1 line).
__device__ __half g_nodes[NUM_NODES * EMB_D];

// Phase 1: build fused node table (fp32 math, fp16 store, x512 pre-scale).
__global__ void build_nodes_kernel(const float* __restrict__ user_emb,
                                   const float* __restrict__ item_emb,
                                   const float* __restrict__ tag_emb,
                                   const float* __restrict__ testid_emb,
                                   const float* __restrict__ bigcat_emb,
                                   const float* __restrict__ daydiff_emb,
                                   const int*  __restrict__ item_tags,
                                   const int*  __restrict__ item_testids,
                                   const int*  __restrict__ item_bigcat,
                                   const int*  __restrict__ user_daydiff) {
    unsigned int t = blockIdx.x * blockDim.x + threadIdx.x;
    unsigned int node = t >> 4;
    unsigned int sub  = t & 15u;
    if (node >= NUM_NODES) return;
    unsigned int off = sub * 4u;

    const float alpha = 1.0f / 3.0f;
    float4 r;
    if (node < N_USER) {
        const float s = 0.5f * alpha * TBL_SCALE;
        int dd = user_daydiff[node];
        float4 u = *(const float4*)(user_emb    + (size_t)node * EMB_D + off);
        float4 d = *(const float4*)(daydiff_emb + (size_t)dd   * EMB_D + off);
        r.x = (u.x + d.x) * s;
        r.y = (u.y + d.y) * s;
        r.z = (u.z + d.z) * s;
        r.w = (u.w + d.w) * s;
    } else {
        const float s = 0.25f * alpha * TBL_SCALE;
        unsigned int it = node - N_USER;
        int tg = item_tags[it];
        int ts = item_testids[it];
        int bc = item_bigcat[it];
        float4 a = *(const float4*)(item_emb   + (size_t)it * EMB_D + off);
        float4 b = *(const float4*)(tag_emb    + (size_t)tg * EMB_D + off);
        float4 c = *(const float4*)(testid_emb + (size_t)ts * EMB_D + off);
        float4 e = *(const float4*)(bigcat_emb + (size_t)bc * EMB_D + off);
        r.x = (a.x + b.x + c.x + e.x) * s;
        r.y = (a.y + b.y + c.y + e.y) * s;
        r.z = (a.z + b.z + c.z + e.z) * s;
        r.w = (a.w + b.w + c.w + e.w) * s;
    }
    __half2 h0 = __floats2half2_rn(r.x, r.y);
    __half2 h1 = __floats2half2_rn(r.z, r.w);
    uint2 packed;
    packed.x = *(const unsigned int*)&h0;
    packed.y = *(const unsigned int*)&h1;
    *(uint2*)((char*)g_nodes + (size_t)node * 128u + sub * 8u) = packed;
}

// half2 partial dot of 16 halves (one uint4 pair): 4 HMUL2 + 3 HADD2.
__device__ __forceinline__ __half2 pdot(uint4 a, uint4 b) {
    const __half2* pa = (const __half2*)&a;
    const __half2* pb = (const __half2*)&b;
    __half2 m0 = __hmul2(pa[0], pb[0]);
    __half2 m1 = __hmul2(pa[1], pb[1]);
    __half2 m2 = __hmul2(pa[2], pb[2]);
    __half2 m3 = __hmul2(pa[3], pb[3]);
    return __hadd2(__hadd2(m0, m1), __hadd2(m2, m3));
}

__device__ __forceinline__ __half2 shfl_h2(__half2 v, int ofs) {
    unsigned int u = *(unsigned int*)&v;
    u = __shfl_xor_sync(0xffffffffu, u, ofs);
    return *(__half2*)&u;
}

// Value-halving reduction of 8 half2 partials over 8 lanes (7 SHFL + 7 HADD2).
// On return lane `sub` holds the full 64-dim sum (as one half2 pair-sum) of
// edge `sub` of the batch.
__device__ __forceinline__ __half2 reduce8(__half2 p0, __half2 p1, __half2 p2, __half2 p3,
                                           __half2 p4, __half2 p5, __half2 p6, __half2 p7,
                                           bool bit2, bool bit1, bool bit0) {
    __half2 w0, w1, w2, w3;
    {
        __half2 q0 = bit2 ? p0 : p4;
        __half2 q1 = bit2 ? p1 : p5;
        __half2 q2 = bit2 ? p2 : p6;
        __half2 q3 = bit2 ? p3 : p7;
        w0 = __hadd2(bit2 ? p4 : p0, shfl_h2(q0, 4));
        w1 = __hadd2(bit2 ? p5 : p1, shfl_h2(q1, 4));
        w2 = __hadd2(bit2 ? p6 : p2, shfl_h2(q2, 4));
        w3 = __hadd2(bit2 ? p7 : p3, shfl_h2(q3, 4));
    }
    __half2 x0, x1;
    {
        __half2 q0 = bit1 ? w0 : w2;
        __half2 q1 = bit1 ? w1 : w3;
        x0 = __hadd2(bit1 ? w2 : w0, shfl_h2(q0, 2));
        x1 = __hadd2(bit1 ? w3 : w1, shfl_h2(q1, 2));
    }
    __half2 q = bit0 ? x0 : x1;
    return __hadd2(bit0 ? x1 : x0, shfl_h2(q, 1));
}

// Phase 2: 16 edges per 8-lane group, two pipelined batches of 8.
// Batch B's 16 gathers are in flight while batch A's reduction tree runs.
__global__ __launch_bounds__(256) void edge_dot_kernel(
        const int4* __restrict__ src4,
        const int4* __restrict__ dst4,
        float* __restrict__ out) {
    unsigned int t = blockIdx.x * blockDim.x + threadIdx.x;
    unsigned int g   = t >> 3;
    unsigned int sub = t & 7u;
    if (g >= N_GROUPS16) return;

    int4 s0 = src4[g * 4u + 0u];
    int4 s1 = src4[g * 4u + 1u];
    int4 s2 = src4[g * 4u + 2u];
    int4 s3 = src4[g * 4u + 3u];
    int4 d0 = dst4[g * 4u + 0u];
    int4 d1 = dst4[g * 4u + 1u];
    int4 d2 = dst4[g * 4u + 2u];
    int4 d3 = dst4[g * 4u + 3u];

    const uint4* np = (const uint4*)g_nodes + sub;   // row = 8 uint4

    // ---- Batch A: edges 0-7 (s0,s1 / d0,d1) ----
    uint4 a0 = np[(unsigned)s0.x * 8u];
    uint4 b0 = np[(unsigned)d0.x * 8u];
    uint4 a1 = np[(unsigned)s0.y * 8u];
    uint4 b1 = np[(unsigned)d0.y * 8u];
    uint4 a2 = np[(unsigned)s0.z * 8u];
    uint4 b2 = np[(unsigned)d0.z * 8u];
    uint4 a3 = np[(unsigned)s0.w * 8u];
    uint4 b3 = np[(unsigned)d0.w * 8u];
    uint4 a4 = np[(unsigned)s1.x * 8u];
    uint4 b4 = np[(unsigned)d1.x * 8u];
    uint4 a5 = np[(unsigned)s1.y * 8u];
    uint4 b5 = np[(unsigned)d1.y * 8u];
    uint4 a6 = np[(unsigned)s1.z * 8u];
    uint4 b6 = np[(unsigned)d1.z * 8u];
    uint4 a7 = np[(unsigned)s1.w * 8u];
    uint4 b7 = np[(unsigned)d1.w * 8u];

    __half2 pA0 = pdot(a0, b0);
    __half2 pA1 = pdot(a1, b1);
    __half2 pA2 = pdot(a2, b2);
    __half2 pA3 = pdot(a3, b3);
    __half2 pA4 = pdot(a4, b4);
    __half2 pA5 = pdot(a5, b5);
    __half2 pA6 = pdot(a6, b6);
    __half2 pA7 = pdot(a7, b7);

    // ---- Batch B: edges 8-15 (s2,s3 / d2,d3) — loads overlap A's tree ----
    uint4 c0 = np[(unsigned)s2.x * 8u];
    uint4 e0 = np[(unsigned)d2.x * 8u];
    uint4 c1 = np[(unsigned)s2.y * 8u];
    uint4 e1 = np[(unsigned)d2.y * 8u];
    uint4 c2 = np[(unsigned)s2.z * 8u];
    uint4 e2 = np[(unsigned)d2.z * 8u];
    uint4 c3 = np[(unsigned)s2.w * 8u];
    uint4 e3 = np[(unsigned)d2.w * 8u];
    uint4 c4 = np[(unsigned)s3.x * 8u];
    uint4 e4 = np[(unsigned)d3.x * 8u];
    uint4 c5 = np[(unsigned)s3.y * 8u];
    uint4 e5 = np[(unsigned)d3.y * 8u];
    uint4 c6 = np[(unsigned)s3.z * 8u];
    uint4 e6 = np[(unsigned)d3.z * 8u];
    uint4 c7 = np[(unsigned)s3.w * 8u];
    uint4 e7 = np[(unsigned)d3.w * 8u];

    bool bit2 = (sub & 4u) != 0u;
    bool bit1 = (sub & 2u) != 0u;
    bool bit0 = (sub & 1u) != 0u;

    __half2 yA = reduce8(pA0, pA1, pA2, pA3, pA4, pA5, pA6, pA7, bit2, bit1, bit0);

    __half2 pB0 = pdot(c0, e0);
    __half2 pB1 = pdot(c1, e1);
    __half2 pB2 = pdot(c2, e2);
    __half2 pB3 = pdot(c3, e3);
    __half2 pB4 = pdot(c4, e4);
    __half2 pB5 = pdot(c5, e5);
    __half2 pB6 = pdot(c6, e6);
    __half2 pB7 = pdot(c7, e7);

    __half2 yB = reduce8(pB0, pB1, pB2, pB3, pB4, pB5, pB6, pB7, bit2, bit1, bit0);

    float2 fA = __half22float2(yA);
    float2 fB = __half22float2(yB);
    out[g * 16u + sub]      = (fA.x + fA.y) * INV_TBL_SCALE2;
    out[g * 16u + 8u + sub] = (fB.x + fB.y) * INV_TBL_SCALE2;
}

extern "C" void kernel_launch(void* const* d_in, const int* in_sizes, int n_in,
                              void* d_out, int out_size) {
    const float* user_emb     = (const float*)d_in[0];
    const float* item_emb     = (const float*)d_in[1];
    const float* tag_emb      = (const float*)d_in[2];
    const float* testid_emb   = (const float*)d_in[3];
    const float* bigcat_emb   = (const float*)d_in[4];
    const float* daydiff_emb  = (const float*)d_in[5];
    const int*   edge_index   = (const int*)d_in[6];   // [2, N_EDGES] int32
    const int*   item_tags    = (const int*)d_in[7];
    const int*   item_testids = (const int*)d_in[8];
    const int*   item_bigcat  = (const int*)d_in[9];
    const int*   user_daydiff = (const int*)d_in[10];

    // Phase 1: 60000 nodes * 16 threads
    {
        unsigned int total = NUM_NODES * 16u;
        unsigned int threads = 256;
        unsigned int blocks = (total + threads - 1) / threads;
        build_nodes_kernel<<<blocks, threads>>>(user_emb, item_emb, tag_emb,
                                                testid_emb, bigcat_emb, daydiff_emb,
                                                item_tags, item_testids, item_bigcat,
                                                user_daydiff);
    }

    // Phase 2: 125K groups * 8 threads = 1M threads
    {
        const int4* src4 = (const int4*)edge_index;
        const int4* dst4 = (const int4*)(edge_index + N_EDGES);
        unsigned int total = N_GROUPS16 * 8u;
        unsigned int threads = 256;
        unsigned int blocks = (total + threads - 1) / threads;
        edge_dot_kernel<<<blocks, threads>>>(src4, dst4, (float*)d_out);
    }
}